// round 15
// baseline (speedup 1.0000x reference)
#include <cuda_runtime.h>
#include <cuda_fp16.h>
#include <float.h>

#define KDIM 256
#define NITER 50
#define NCONS 512
#define NTH 576
#define BPC 4
#define NBUF 2
#define CHUNK_BYTES 16384        // 16 rows x 256 fp32
#define CHUNK_FLOATS 4096

// Shared memory layout (bytes) — total 232384 <= 232448 cap
#define CS_OFF   0               // 131072: 256 rows x 64 uint2 (fp16), XOR-swizzled
#define SC_OFF   131072          // 65536: scratch, upper 128 rows of NEXT batch (fp16 C)
#define STG_OFF  196608          // 32768: 2 x 16KB fp32 staging ring
#define FS_OFF   229376          // 1024: f = 0.5*scores (current working batch)
#define GV_OFF   230400          // 1024: row sums
#define WSA_OFF  231424          // 192: upper-half partials (sum/tr/min x16)
#define WSB_OFF  231616          // 192: lower-half partials
#define CN_OFF   231808          // 32: A, Bc, eps, Cc
#define GT_OFF   231840          // 400: 50 x float2
#define MB_OFF   232240          // 16: 2 data mbarriers
#define MC_OFF   232256          // 16: 2 consumption mbarriers
#define FL_OFF   232272          // 16
#define RB_OFF   232288          // 96: 18 floats reduce scratch
#define SMEM_BYTES 232384

__device__ float g_scratch[1024];
__device__ unsigned int g_count = 0;

__device__ __forceinline__ float ex2f(float x) {
    float y;
    asm("ex2.approx.ftz.f32 %0, %1;" : "=f"(y) : "f"(x));
    return y;
}
__device__ __forceinline__ void mbar_init(unsigned mbar, unsigned cnt) {
    asm volatile("mbarrier.init.shared::cta.b64 [%0], %1;" :: "r"(mbar), "r"(cnt) : "memory");
}
__device__ __forceinline__ void mbar_expect(unsigned mbar, unsigned bytes) {
    asm volatile("mbarrier.arrive.expect_tx.shared::cta.b64 _, [%0], %1;"
                 :: "r"(mbar), "r"(bytes) : "memory");
}
__device__ __forceinline__ void mbar_arrive(unsigned mbar) {
    asm volatile("mbarrier.arrive.shared::cta.b64 _, [%0];" :: "r"(mbar) : "memory");
}
__device__ __forceinline__ void mbar_wait(unsigned mbar, unsigned phase) {
    asm volatile(
        "{\n\t"
        ".reg .pred P;\n\t"
        "LW_%=:\n\t"
        "mbarrier.try_wait.parity.shared::cta.b64 P, [%0], %1;\n\t"
        "@!P bra LW_%=;\n\t"
        "}\n"
        :: "r"(mbar), "r"(phase) : "memory");
}
__device__ __forceinline__ void tma_1d(unsigned dst, const void* src, unsigned bytes, unsigned mbar) {
    asm volatile(
        "cp.async.bulk.shared::cluster.global.mbarrier::complete_tx::bytes [%0], [%1], %2, [%3];"
        :: "r"(dst), "l"(src), "r"(bytes), "r"(mbar) : "memory");
}

// Producer (single thread): issue chunks [s0, s0+cnt), each gated on consumption
// of chunk s-NBUF (same staging slot). All gates clear within the calling phase.
__device__ __forceinline__ void produce_phase(int s0, int cnt, int total, const float* Cbase,
                                              unsigned stgB, unsigned mbB, unsigned mcB)
{
    #pragma unroll
    for (int i = 0; i < cnt; i++) {
        const int s = s0 + i;
        if (s < total) {
            if (s >= NBUF) {
                const int g = s - NBUF;
                mbar_wait(mcB + 8u * (g & 1), (unsigned)((g >> 1) & 1));
            }
            const int slot = s & 1;
            mbar_expect(mbB + 8u * slot, CHUNK_BYTES);
            tma_1d(stgB + slot * CHUNK_BYTES, Cbase + (size_t)s * CHUNK_FLOATS,
                   CHUNK_BYTES, mbB + 8u * slot);
        }
    }
}

// Consumers (warps 0-15): drain 8 chunks starting at gc0 into dest (Cs or SC),
// rows rowbase + c*16 + wid, accumulating sum/trace/min partials into ws*.
__device__ __forceinline__ void convert_phase(const unsigned char* smraw, uint2* dest,
                                              const float* fs, int gc0, int rowbase,
                                              int wid, int lane, unsigned mbB, unsigned mcB,
                                              float* wsS, float* wsT, float* wsM)
{
    const float4* fs4 = (const float4*)fs;
    const int c40 = lane, c41 = lane + 32;
    const float4 fj0 = fs4[c40];
    const float4 fj1 = fs4[c41];
    float psum = 0.f, ptrc = 0.f, pmin = FLT_MAX;
    #pragma unroll
    for (int c = 0; c < 8; c++) {
        const int gc = gc0 + c;
        const int slot = gc & 1;
        mbar_wait(mbB + 8u * slot, (unsigned)((gc >> 1) & 1));
        const float4* stg = (const float4*)(smraw + STG_OFF + slot * CHUNK_BYTES);
        const int r = rowbase + c * 16 + wid;
        const float fi = fs[r];
        float4 cc0 = stg[wid * 64 + c40];
        float4 cc1 = stg[wid * 64 + c41];

        float v0 = fminf(fj0.x + cc0.x, fj0.y + cc0.y);
        float v1 = fminf(fj0.z + cc0.z, fj0.w + cc0.w);
        float v2 = fminf(fj1.x + cc1.x, fj1.y + cc1.y);
        float v3 = fminf(fj1.z + cc1.z, fj1.w + cc1.w);
        pmin = fminf(pmin, fi + fminf(fminf(v0, v1), fminf(v2, v3)));
        psum += ((cc0.x + cc0.y) + (cc0.z + cc0.w)) + ((cc1.x + cc1.y) + (cc1.z + cc1.w));
        int d0 = r - 4 * c40;
        if ((unsigned)d0 < 4u)
            ptrc += (d0 == 0) ? cc0.x : (d0 == 1) ? cc0.y : (d0 == 2) ? cc0.z : cc0.w;
        int d1 = r - 4 * c41;
        if ((unsigned)d1 < 4u)
            ptrc += (d1 == 0) ? cc1.x : (d1 == 1) ? cc1.y : (d1 == 2) ? cc1.z : cc1.w;

        __half2 h00 = __floats2half2_rn(cc0.x, cc0.y);
        __half2 h01 = __floats2half2_rn(cc0.z, cc0.w);
        __half2 h10 = __floats2half2_rn(cc1.x, cc1.y);
        __half2 h11 = __floats2half2_rn(cc1.z, cc1.w);
        uint2 s0v, s1v;
        s0v.x = *(unsigned*)&h00; s0v.y = *(unsigned*)&h01;
        s1v.x = *(unsigned*)&h10; s1v.y = *(unsigned*)&h11;
        const int sw = r & 31;
        dest[r * 64 + (c40 ^ sw)] = s0v;
        dest[r * 64 + (c41 ^ sw)] = s1v;

        if (lane == 0) mbar_arrive(mcB + 8u * slot);
    }
    #pragma unroll
    for (int o = 16; o; o >>= 1) {
        psum += __shfl_xor_sync(0xffffffffu, psum, o);
        ptrc += __shfl_xor_sync(0xffffffffu, ptrc, o);
        pmin  = fminf(pmin, __shfl_xor_sync(0xffffffffu, pmin, o));
    }
    if (lane == 0) { wsS[wid] = psum; wsT[wid] = ptrc; wsM[wid] = pmin; }
}

// Frank-Wolfe: single warp, packed-key argmin (1 REDUX/iter), PRMT half select.
__device__ __forceinline__ void run_fw(const uint2* __restrict__ Cs, const float* __restrict__ gv,
                                       const float* __restrict__ cons, const float2* __restrict__ gtab,
                                       const float* __restrict__ scores, const int* __restrict__ targets,
                                       int b, int lane)
{
    float gr[8], al[8];
    #pragma unroll
    for (int m = 0; m < 8; m++) { gr[m] = gv[lane + 32 * m]; al[m] = 0.00390625f; }
    for (int it = 0; it < NITER; it++) {
        float2 gg = gtab[it];
        unsigned key = 0xffffffffu;
        #pragma unroll
        for (int m = 0; m < 8; m++)
            key = min(key, (__float_as_uint(gr[m]) & 0xffffff00u) | (unsigned)(lane + 32 * m));
        unsigned kmin = __reduce_min_sync(0xffffffffu, key);
        unsigned idx = kmin & 0xffu;
        unsigned pw  = (idx >> 2) ^ (unsigned)lane;
        unsigned ctl = (idx & 3u) * 0x22u + 0x10u;
        #pragma unroll
        for (int m = 0; m < 8; m++) {
            unsigned row = (unsigned)lane + 32u * m;
            uint2 u = Cs[row * 64u + pw];
            unsigned hw = __byte_perm(u.x, u.y, ctl);
            float colv = __half2float(__ushort_as_half((unsigned short)hw));
            gr[m] = fmaf(gg.x, colv, gg.y * gr[m]);
            al[m] = fmaf(gg.y, al[m], (row == idx) ? gg.x : 0.0f);
        }
    }
    float dot = 0.f;
    #pragma unroll
    for (int m = 0; m < 8; m++) dot = fmaf(al[m], gr[m], dot);
    #pragma unroll
    for (int o = 16; o; o >>= 1) dot += __shfl_xor_sync(0xffffffffu, dot, o);
    if (lane == 0) {
        float conj = cons[3] - cons[2] * __logf(dot);
        g_scratch[b] = conj - scores[b * KDIM + targets[b]];
    }
}

extern "C" __global__ void __launch_bounds__(NTH, 1)
cacis_fused(const float* __restrict__ scores, const int* __restrict__ targets,
            const float* __restrict__ C, float* __restrict__ out, int B)
{
    extern __shared__ unsigned char smraw[];
    uint2*  Csp  = (uint2*)(smraw + CS_OFF);
    uint2*  SCp  = (uint2*)(smraw + SC_OFF);
    float*  fs   = (float*)(smraw + FS_OFF);
    float*  gv   = (float*)(smraw + GV_OFF);
    float*  wsAS = (float*)(smraw + WSA_OFF);
    float*  wsAT = (float*)(smraw + WSA_OFF + 64);
    float*  wsAM = (float*)(smraw + WSA_OFF + 128);
    float*  wsBS = (float*)(smraw + WSB_OFF);
    float*  wsBT = (float*)(smraw + WSB_OFF + 64);
    float*  wsBM = (float*)(smraw + WSB_OFF + 128);
    float*  cons = (float*)(smraw + CN_OFF);
    float2* gtab = (float2*)(smraw + GT_OFF);
    int*    flg  = (int*)(smraw + FL_OFF);
    float*  rbuf = (float*)(smraw + RB_OFF);
    const float4* fs4 = (const float4*)fs;

    const unsigned smem_base = (unsigned)__cvta_generic_to_shared(smraw);
    const unsigned stgB = smem_base + STG_OFF;
    const unsigned mbB  = smem_base + MB_OFF;
    const unsigned mcB  = smem_base + MC_OFF;

    const int t = threadIdx.x, lane = t & 31, wid = t >> 5;
    const int b0 = blockIdx.x * BPC;
    const int nb = min(BPC, B - b0);
    const int total = nb * 16;
    const float* Cbase = C + (size_t)b0 * (KDIM * KDIM);

    // ---- prologue ----
    if (t == 0) {
        mbar_init(mbB, 1);      mbar_init(mbB + 8, 1);
        mbar_init(mcB, 16);     mbar_init(mcB + 8, 16);
    }
    if (t < KDIM) fs[t] = 0.5f * scores[(size_t)b0 * KDIM + t];
    if (t < NITER) { float g = 2.0f / (float)(t + 2); gtab[t] = make_float2(g, 1.0f - g); }
    __syncthreads();

    // P3(-1): convert upper half of batch 0 into SC
    if (wid < 16)
        convert_phase(smraw, SCp, fs, 0, 0, wid, lane, mbB, mcB, wsAS, wsAT, wsAM);
    else if (wid == 16 && lane == 0)
        produce_phase(0, 8, total, Cbase, stgB, mbB, mcB);
    __syncthreads();

    for (int k = 0; k < nb; k++) {
        // ===== P1: convert lower half of batch k into Cs; warp17 zeroes gv =====
        if (wid < 16)
            convert_phase(smraw, Csp, fs, k * 16 + 8, 128, wid, lane, mbB, mcB, wsBS, wsBT, wsBM);
        else if (wid == 16) {
            if (lane == 0) produce_phase(k * 16 + 8, 8, total, Cbase, stgB, mbB, mcB);
        } else {
            #pragma unroll
            for (int i = lane; i < KDIM; i += 32) gv[i] = 0.f;
        }
        __syncthreads();

        // ===== P2a: finalize consts (per consumer warp) + transform; warp17 preloads fs(k+1) =====
        float nfs[8];
        if (t < NCONS) {
            float vS = (lane < 16) ? wsAS[lane] : wsBS[lane - 16];
            float vT = (lane < 16) ? wsAT[lane] : wsBT[lane - 16];
            float vM = (lane < 16) ? wsAM[lane] : wsBM[lane - 16];
            #pragma unroll
            for (int o = 16; o; o >>= 1) {
                vS += __shfl_xor_sync(0xffffffffu, vS, o);
                vT += __shfl_xor_sync(0xffffffffu, vT, o);
                vM  = fminf(vM, __shfl_xor_sync(0xffffffffu, vM, o));
            }
            float eps = fmaxf((vS - vT) / 65280.0f, 1e-8f);   // K*K-K
            float k2  = 1.4426950408889634f / eps;            // log2(e)/eps
            const float A  = -k2;
            const float Bc = fmaf(vM, k2, 14.0f);             // M' = M * 2^14
            if (t == 0) {
                cons[0] = A; cons[1] = Bc; cons[2] = eps;
                cons[3] = fmaf(9.7040605278392342f, eps, vM); // mn + 14*ln2*eps
            }
            const int i = t & 255, hh = t >> 8, sw = i & 31;
            const uint2* srcp = (i < 128) ? (SCp + i * 64) : (Csp + i * 64);
            uint2* dstp = Csp + i * 64;
            const float fiAB = fmaf(fs[i], A, Bc);
            float rs = 0.f;
            #pragma unroll 8
            for (int ww = hh * 32; ww < hh * 32 + 32; ww++) {
                const int pa = ww ^ sw;
                uint2 uu = srcp[pa];
                float2 c01 = __half22float2(*(__half2*)&uu.x);
                float2 c23 = __half22float2(*(__half2*)&uu.y);
                float4 fj = fs4[ww];
                float m0 = ex2f(fmaf(c01.x, A, fmaf(fj.x, A, fiAB)));
                float m1 = ex2f(fmaf(c01.y, A, fmaf(fj.y, A, fiAB)));
                float m2 = ex2f(fmaf(c23.x, A, fmaf(fj.z, A, fiAB)));
                float m3 = ex2f(fmaf(c23.y, A, fmaf(fj.w, A, fiAB)));
                rs += (m0 + m1) + (m2 + m3);
                __half2 o01 = __floats2half2_rn(m0, m1);
                __half2 o23 = __floats2half2_rn(m2, m3);
                uint2 st;
                st.x = *(unsigned*)&o01;
                st.y = *(unsigned*)&o23;
                dstp[pa] = st;
            }
            atomicAdd(&gv[i], rs);                 // exactly 2 commutative adds per row
        } else if (wid == 17 && k + 1 < nb) {
            #pragma unroll
            for (int m = 0; m < 8; m++)
                nfs[m] = 0.5f * scores[(size_t)(b0 + k + 1) * KDIM + lane + 32 * m];
        }
        __syncthreads();

        // ===== P2b: publish fs(k+1) =====
        if (wid == 17 && k + 1 < nb) {
            #pragma unroll
            for (int m = 0; m < 8; m++) fs[lane + 32 * m] = nfs[m];
        }
        __syncthreads();

        // ===== P3: FW(k) on warp17 || convert upper half of batch k+1 into SC =====
        if (wid == 17) {
            run_fw(Csp, gv, cons, gtab, scores, targets, b0 + k, lane);
        } else if (k + 1 < nb) {
            if (wid < 16)
                convert_phase(smraw, SCp, fs, (k + 1) * 16, 0, wid, lane, mbB, mcB, wsAS, wsAT, wsAM);
            else if (lane == 0)
                produce_phase((k + 1) * 16, 8, total, Cbase, stgB, mbB, mcB);
        }
        __syncthreads();
    }

    // ---- fused cross-CTA reduction: last CTA sums g_scratch in fixed order ----
    if (t == 0) {
        __threadfence();
        unsigned prev = atomicAdd(&g_count, 1u);
        *flg = (prev == gridDim.x - 1) ? 1 : 0;
    }
    __syncthreads();
    if (*flg) {
        if (t == 0) g_count = 0;                   // reset for next graph replay
        __threadfence();
        float s = 0.f;
        for (int i = t; i < B; i += NTH) s += __ldcg(&g_scratch[i]);
        #pragma unroll
        for (int o = 16; o; o >>= 1) s += __shfl_down_sync(0xffffffffu, s, o);
        if (lane == 0) rbuf[wid] = s;
        __syncthreads();
        if (t == 0) {
            float tot = 0.f;
            #pragma unroll
            for (int w = 0; w < 18; w++) tot += rbuf[w];
            out[0] = tot / (float)B;
        }
    }
}

extern "C" void kernel_launch(void* const* d_in, const int* in_sizes, int n_in,
                              void* d_out, int out_size)
{
    const float* scores  = (const float*)d_in[0];
    const int*   targets = (const int*)d_in[1];
    const float* C       = (const float*)d_in[2];
    const int B = in_sizes[1];
    const int grid = (B + BPC - 1) / BPC;

    cudaFuncSetAttribute(cacis_fused, cudaFuncAttributeMaxDynamicSharedMemorySize, SMEM_BYTES);
    cacis_fused<<<grid, NTH, SMEM_BYTES>>>(scores, targets, C, (float*)d_out, B);
}

// round 17
// speedup vs baseline: 1.1460x; 1.1460x over previous
#include <cuda_runtime.h>
#include <cuda_fp16.h>
#include <float.h>

#define KDIM 256
#define NITER 50
#define NCONS 512
#define NTH 576
#define BPC 4
#define NBUF 5
#define CHUNK_BYTES 16384        // 16 rows x 256 fp32
#define CHUNK_FLOATS 4096

// Shared memory layout (bytes) — total 216896, under 232448 cap
#define CS_OFF   0               // 131072: 256 rows x 64 uint2 (fp16 M'), XOR-swizzled
#define STG_OFF  131072          // 81920: 5 x 16KB fp32 staging ring
#define FS_OFF   212992          // 2048: 2 x 256 floats f = 0.5*scores (double-buffered)
#define GV_OFF   215040          // 1024: row sums (direct stores, no atomics)
#define WS_OFF   216064          // 192: sum/trace/min x16 warps
#define CN_OFF   216256          // 32: A, Bc, eps, Cc
#define GT_OFF   216288          // 400: 50 x float2
#define MB_OFF   216704          // 40: 5 data mbarriers
#define MC_OFF   216744          // 40: 5 consumption mbarriers
#define FL_OFF   216784          // 16
#define RB_OFF   216800          // 96: 18 floats reduce scratch
#define SMEM_BYTES 216896

__device__ float g_scratch[1024];
__device__ unsigned int g_count = 0;

__device__ __forceinline__ float ex2f(float x) {
    float y;
    asm("ex2.approx.ftz.f32 %0, %1;" : "=f"(y) : "f"(x));
    return y;
}
__device__ __forceinline__ void mbar_init(unsigned mbar, unsigned cnt) {
    asm volatile("mbarrier.init.shared::cta.b64 [%0], %1;" :: "r"(mbar), "r"(cnt) : "memory");
}
__device__ __forceinline__ void mbar_expect(unsigned mbar, unsigned bytes) {
    asm volatile("mbarrier.arrive.expect_tx.shared::cta.b64 _, [%0], %1;"
                 :: "r"(mbar), "r"(bytes) : "memory");
}
__device__ __forceinline__ void mbar_arrive(unsigned mbar) {
    asm volatile("mbarrier.arrive.shared::cta.b64 _, [%0];" :: "r"(mbar) : "memory");
}
__device__ __forceinline__ void mbar_wait(unsigned mbar, unsigned phase) {
    asm volatile(
        "{\n\t"
        ".reg .pred P;\n\t"
        "LW_%=:\n\t"
        "mbarrier.try_wait.parity.shared::cta.b64 P, [%0], %1;\n\t"
        "@!P bra LW_%=;\n\t"
        "}\n"
        :: "r"(mbar), "r"(phase) : "memory");
}
__device__ __forceinline__ void tma_1d(unsigned dst, const void* src, unsigned bytes, unsigned mbar) {
    asm volatile(
        "cp.async.bulk.shared::cluster.global.mbarrier::complete_tx::bytes [%0], [%1], %2, [%3];"
        :: "r"(dst), "l"(src), "r"(bytes), "r"(mbar) : "memory");
}

// Chunk-use u -> source chunk: batch (u>>5), chunk (u&15). A-pass uses 32k..32k+15,
// B-pass uses 32k+16..32k+31, SAME addresses (B re-reads from L2).
__device__ __forceinline__ void produce_uses(int u0, int cnt, int total, const float* Cbase,
                                             unsigned stgB, unsigned mbB, unsigned mcB)
{
    #pragma unroll
    for (int i = 0; i < cnt; i++) {
        const int u = u0 + i;
        if (u < total) {
            if (u >= NBUF) {
                const int g = u - NBUF;
                mbar_wait(mcB + 8u * (g % NBUF), (unsigned)((g / NBUF) & 1));
            }
            const int slot = u % NBUF;
            mbar_expect(mbB + 8u * slot, CHUNK_BYTES);
            tma_1d(stgB + slot * CHUNK_BYTES,
                   Cbase + (size_t)(((u >> 5) << 4) + (u & 15)) * CHUNK_FLOATS,
                   CHUNK_BYTES, mbB + 8u * slot);
        }
    }
}

// A-pass (warps 0-15): stats only — sum/trace/min of (f_i+f_j+C). No smem stores.
__device__ __forceinline__ void stats_pass(const unsigned char* smraw, const float* fs,
                                           int u0, int wid, int lane,
                                           unsigned mbB, unsigned mcB,
                                           float* wsS, float* wsT, float* wsM)
{
    const float4* fs4 = (const float4*)fs;
    const int c40 = lane, c41 = lane + 32;
    const float4 fj0 = fs4[c40];
    const float4 fj1 = fs4[c41];
    float psum = 0.f, ptrc = 0.f, pmin = FLT_MAX;
    #pragma unroll
    for (int c = 0; c < 16; c++) {
        const int u = u0 + c;
        mbar_wait(mbB + 8u * (u % NBUF), (unsigned)((u / NBUF) & 1));
        const float4* stg = (const float4*)(smraw + STG_OFF + (u % NBUF) * CHUNK_BYTES);
        const int r = c * 16 + wid;
        const float fi = fs[r];
        float4 cc0 = stg[wid * 64 + c40];
        float4 cc1 = stg[wid * 64 + c41];

        float v0 = fminf(fj0.x + cc0.x, fj0.y + cc0.y);
        float v1 = fminf(fj0.z + cc0.z, fj0.w + cc0.w);
        float v2 = fminf(fj1.x + cc1.x, fj1.y + cc1.y);
        float v3 = fminf(fj1.z + cc1.z, fj1.w + cc1.w);
        pmin = fminf(pmin, fi + fminf(fminf(v0, v1), fminf(v2, v3)));
        psum += ((cc0.x + cc0.y) + (cc0.z + cc0.w)) + ((cc1.x + cc1.y) + (cc1.z + cc1.w));
        int d0 = r - 4 * c40;
        if ((unsigned)d0 < 4u)
            ptrc += (d0 == 0) ? cc0.x : (d0 == 1) ? cc0.y : (d0 == 2) ? cc0.z : cc0.w;
        int d1 = r - 4 * c41;
        if ((unsigned)d1 < 4u)
            ptrc += (d1 == 0) ? cc1.x : (d1 == 1) ? cc1.y : (d1 == 2) ? cc1.z : cc1.w;

        if (lane == 0) mbar_arrive(mcB + 8u * (u % NBUF));
    }
    #pragma unroll
    for (int o = 16; o; o >>= 1) {
        psum += __shfl_xor_sync(0xffffffffu, psum, o);
        ptrc += __shfl_xor_sync(0xffffffffu, ptrc, o);
        pmin  = fminf(pmin, __shfl_xor_sync(0xffffffffu, pmin, o));
    }
    if (lane == 0) { wsS[wid] = psum; wsT[wid] = ptrc; wsM[wid] = pmin; }
}

// Frank-Wolfe: single warp, packed-key argmin (1 REDUX/iter), PRMT half select.
__device__ __forceinline__ void run_fw(const uint2* __restrict__ Cs, const float* __restrict__ gv,
                                       const float* __restrict__ cons, const float2* __restrict__ gtab,
                                       const float* __restrict__ scores, const int* __restrict__ targets,
                                       int b, int lane)
{
    float gr[8], al[8];
    #pragma unroll
    for (int m = 0; m < 8; m++) { gr[m] = gv[lane + 32 * m]; al[m] = 0.00390625f; }
    for (int it = 0; it < NITER; it++) {
        float2 gg = gtab[it];
        unsigned key = 0xffffffffu;
        #pragma unroll
        for (int m = 0; m < 8; m++)
            key = min(key, (__float_as_uint(gr[m]) & 0xffffff00u) | (unsigned)(lane + 32 * m));
        unsigned kmin = __reduce_min_sync(0xffffffffu, key);
        unsigned idx = kmin & 0xffu;
        unsigned pw  = (idx >> 2) ^ (unsigned)lane;
        unsigned ctl = (idx & 3u) * 0x22u + 0x10u;
        #pragma unroll
        for (int m = 0; m < 8; m++) {
            unsigned row = (unsigned)lane + 32u * m;
            uint2 u = Cs[row * 64u + pw];
            unsigned hw = __byte_perm(u.x, u.y, ctl);
            float colv = __half2float(__ushort_as_half((unsigned short)hw));
            gr[m] = fmaf(gg.x, colv, gg.y * gr[m]);
            al[m] = fmaf(gg.y, al[m], (row == idx) ? gg.x : 0.0f);
        }
    }
    float dot = 0.f;
    #pragma unroll
    for (int m = 0; m < 8; m++) dot = fmaf(al[m], gr[m], dot);
    #pragma unroll
    for (int o = 16; o; o >>= 1) dot += __shfl_xor_sync(0xffffffffu, dot, o);
    if (lane == 0) {
        float conj = cons[3] - cons[2] * __logf(dot);
        g_scratch[b] = conj - scores[b * KDIM + targets[b]];
    }
}

extern "C" __global__ void __launch_bounds__(NTH, 1)
cacis_fused(const float* __restrict__ scores, const int* __restrict__ targets,
            const float* __restrict__ C, float* __restrict__ out, int B)
{
    extern __shared__ unsigned char smraw[];
    uint2*  Csp  = (uint2*)(smraw + CS_OFF);
    float*  fsb  = (float*)(smraw + FS_OFF);
    float*  gv   = (float*)(smraw + GV_OFF);
    float*  wsS  = (float*)(smraw + WS_OFF);
    float*  wsT  = (float*)(smraw + WS_OFF + 64);
    float*  wsM  = (float*)(smraw + WS_OFF + 128);
    float*  cons = (float*)(smraw + CN_OFF);
    float2* gtab = (float2*)(smraw + GT_OFF);
    int*    flg  = (int*)(smraw + FL_OFF);
    float*  rbuf = (float*)(smraw + RB_OFF);

    const unsigned smem_base = (unsigned)__cvta_generic_to_shared(smraw);
    const unsigned stgB = smem_base + STG_OFF;
    const unsigned mbB  = smem_base + MB_OFF;
    const unsigned mcB  = smem_base + MC_OFF;

    const int t = threadIdx.x, lane = t & 31, wid = t >> 5;
    const int b0 = blockIdx.x * BPC;
    const int nb = min(BPC, B - b0);
    const int total = 32 * nb;               // A + B uses
    const float* Cbase = C + (size_t)b0 * (KDIM * KDIM);

    // ---- prologue ----
    if (t == 0) {
        #pragma unroll
        for (int i = 0; i < NBUF; i++) { mbar_init(mbB + 8u * i, 1); mbar_init(mcB + 8u * i, 16); }
    }
    if (t < KDIM) fsb[t] = 0.5f * scores[(size_t)b0 * KDIM + t];
    if (t < NITER) { float g = 2.0f / (float)(t + 2); gtab[t] = make_float2(g, 1.0f - g); }
    __syncthreads();

    // A(0): stats of batch 0 (uses 0..15)
    if (wid < 16)
        stats_pass(smraw, fsb, 0, wid, lane, mbB, mcB, wsS, wsT, wsM);
    else if (wid == 16 && lane == 0)
        produce_uses(0, 16, total, Cbase, stgB, mbB, mcB);
    __syncthreads();

    for (int k = 0; k < nb; k++) {
        const int cur = k & 1;
        const float* fs = fsb + cur * KDIM;
        const int u0B = 32 * k + 16;

        // ===== B(k): L2 re-read -> exp -> Cs + row sums; consts finalized here =====
        if (wid < 16) {
            // all-lane butterfly over 16 warp partials
            float vS = (lane < 16) ? wsS[lane] : 0.f;
            float vT = (lane < 16) ? wsT[lane] : 0.f;
            float vM = (lane < 16) ? wsM[lane] : FLT_MAX;
            #pragma unroll
            for (int o = 16; o; o >>= 1) {
                vS += __shfl_xor_sync(0xffffffffu, vS, o);
                vT += __shfl_xor_sync(0xffffffffu, vT, o);
                vM  = fminf(vM, __shfl_xor_sync(0xffffffffu, vM, o));
            }
            float eps = fmaxf((vS - vT) / 65280.0f, 1e-8f);   // K*K-K
            float k2  = 1.4426950408889634f / eps;            // log2(e)/eps
            const float A  = -k2;
            const float Bc = fmaf(vM, k2, 14.0f);             // M' = M * 2^14
            if (t == 0) {
                cons[0] = A; cons[1] = Bc; cons[2] = eps;
                cons[3] = fmaf(9.7040605278392342f, eps, vM); // mn + 14*ln2*eps
            }
            const float4* fs4 = (const float4*)fs;
            const int c40 = lane, c41 = lane + 32;
            float4 fj0 = fs4[c40];
            float4 fj1 = fs4[c41];
            const float b0x = fmaf(fj0.x, A, Bc), b0y = fmaf(fj0.y, A, Bc);
            const float b0z = fmaf(fj0.z, A, Bc), b0w = fmaf(fj0.w, A, Bc);
            const float b1x = fmaf(fj1.x, A, Bc), b1y = fmaf(fj1.y, A, Bc);
            const float b1z = fmaf(fj1.z, A, Bc), b1w = fmaf(fj1.w, A, Bc);
            #pragma unroll
            for (int c = 0; c < 16; c++) {
                const int u = u0B + c;
                mbar_wait(mbB + 8u * (u % NBUF), (unsigned)((u / NBUF) & 1));
                const float4* stg = (const float4*)(smraw + STG_OFF + (u % NBUF) * CHUNK_BYTES);
                const int r = c * 16 + wid;
                const float fiA = fs[r] * A;
                float4 cc0 = stg[wid * 64 + c40];
                float4 cc1 = stg[wid * 64 + c41];
                float m0 = ex2f(fmaf(cc0.x, A, fiA + b0x));
                float m1 = ex2f(fmaf(cc0.y, A, fiA + b0y));
                float m2 = ex2f(fmaf(cc0.z, A, fiA + b0z));
                float m3 = ex2f(fmaf(cc0.w, A, fiA + b0w));
                float m4 = ex2f(fmaf(cc1.x, A, fiA + b1x));
                float m5 = ex2f(fmaf(cc1.y, A, fiA + b1y));
                float m6 = ex2f(fmaf(cc1.z, A, fiA + b1z));
                float m7 = ex2f(fmaf(cc1.w, A, fiA + b1w));
                float rs = ((m0 + m1) + (m2 + m3)) + ((m4 + m5) + (m6 + m7));
                __half2 h01 = __floats2half2_rn(m0, m1);
                __half2 h23 = __floats2half2_rn(m2, m3);
                __half2 h45 = __floats2half2_rn(m4, m5);
                __half2 h67 = __floats2half2_rn(m6, m7);
                uint2 s0v, s1v;
                s0v.x = *(unsigned*)&h01; s0v.y = *(unsigned*)&h23;
                s1v.x = *(unsigned*)&h45; s1v.y = *(unsigned*)&h67;
                const int sw = r & 31;
                Csp[r * 64 + (c40 ^ sw)] = s0v;
                Csp[r * 64 + (c41 ^ sw)] = s1v;
                if (lane == 0) mbar_arrive(mcB + 8u * (u % NBUF));
                // warp-wide row sum (all 32 lanes share row r)
                #pragma unroll
                for (int o = 16; o; o >>= 1) rs += __shfl_xor_sync(0xffffffffu, rs, o);
                if (lane == 0) gv[r] = rs;
            }
        } else if (wid == 16) {
            if (lane == 0) produce_uses(u0B, 16, total, Cbase, stgB, mbB, mcB);
        } else if (k + 1 < nb) {
            // warp 17: load fs(k+1) into the other buffer
            #pragma unroll
            for (int m = 0; m < 8; m++)
                fsb[(cur ^ 1) * KDIM + lane + 32 * m] =
                    0.5f * scores[(size_t)(b0 + k + 1) * KDIM + lane + 32 * m];
        }
        __syncthreads();

        // ===== overlap: FW(k) on warp 17 || A(k+1) stats on warps 0-16 =====
        if (wid == 17) {
            run_fw(Csp, gv, cons, gtab, scores, targets, b0 + k, lane);
        } else if (k + 1 < nb) {
            if (wid < 16)
                stats_pass(smraw, fsb + (cur ^ 1) * KDIM, 32 * (k + 1), wid, lane,
                           mbB, mcB, wsS, wsT, wsM);
            else if (lane == 0)
                produce_uses(32 * (k + 1), 16, total, Cbase, stgB, mbB, mcB);
        }
        __syncthreads();
    }

    // ---- fused cross-CTA reduction: last CTA sums g_scratch in fixed order ----
    if (t == 0) {
        __threadfence();
        unsigned prev = atomicAdd(&g_count, 1u);
        *flg = (prev == gridDim.x - 1) ? 1 : 0;
    }
    __syncthreads();
    if (*flg) {
        if (t == 0) g_count = 0;                   // reset for next graph replay
        __threadfence();
        float s = 0.f;
        for (int i = t; i < B; i += NTH) s += __ldcg(&g_scratch[i]);
        #pragma unroll
        for (int o = 16; o; o >>= 1) s += __shfl_down_sync(0xffffffffu, s, o);
        if (lane == 0) rbuf[wid] = s;
        __syncthreads();
        if (t == 0) {
            float tot = 0.f;
            #pragma unroll
            for (int w = 0; w < 18; w++) tot += rbuf[w];
            out[0] = tot / (float)B;
        }
    }
}

extern "C" void kernel_launch(void* const* d_in, const int* in_sizes, int n_in,
                              void* d_out, int out_size)
{
    const float* scores  = (const float*)d_in[0];
    const int*   targets = (const int*)d_in[1];
    const float* C       = (const float*)d_in[2];
    const int B = in_sizes[1];
    const int grid = (B + BPC - 1) / BPC;

    cudaFuncSetAttribute(cacis_fused, cudaFuncAttributeMaxDynamicSharedMemorySize, SMEM_BYTES);
    cacis_fused<<<grid, NTH, SMEM_BYTES>>>(scores, targets, C, (float*)d_out, B);
}